// round 3
// baseline (speedup 1.0000x reference)
#include <cuda_runtime.h>

// EquiLocalPatOrientConvolution: B=2, I=32, O=64, D=H=W=48, K=5 (pad 2).
// filter = Y0 * sum_p W[o,i,p] * radial_mask_p (masks partition the 125 taps).
// Fused per-tile: radial sums (10 r^2 classes) + channel-mix GEMM (f32x2 FMA),
// software-pipelined so radial(ci+1) [LSU] overlaps GEMM(ci) [FMA]. 1 bar/ci.

#define DIMS   48
#define TILE   8
#define HALO   12
#define NI     32
#define NO     64
#define NP     10
#define Y0C    0.28209479177387814f
#define NTHR   512
#define NVOX   512

__device__ __host__ constexpr int p_of_r2(int r2) {
    return r2 <= 6 ? r2 : (r2 == 8 ? 7 : (r2 == 9 ? 8 : 9));
}

#define WS_FLOATS  (NI * NP * NO)        // 20480
#define XS_FLOATS  (HALO * HALO * HALO)  // 1728
#define YS_FLOATS  (NP * NVOX)           // 5120
#define SMEM_BYTES ((WS_FLOATS + 2 * XS_FLOATS + 2 * YS_FLOATS) * 4)  // 136704

__device__ __forceinline__ float2 ffma2(float2 a, float2 b, float2 c) {
    unsigned long long ua = *reinterpret_cast<unsigned long long*>(&a);
    unsigned long long ub = *reinterpret_cast<unsigned long long*>(&b);
    unsigned long long uc = *reinterpret_cast<unsigned long long*>(&c);
    unsigned long long ud;
    asm("fma.rn.f32x2 %0, %1, %2, %3;" : "=l"(ud) : "l"(ua), "l"(ub), "l"(uc));
    return *reinterpret_cast<float2*>(&ud);
}

__global__ void __launch_bounds__(NTHR, 1)
econv_kernel(const float* __restrict__ x,
             const float* __restrict__ wg,
             const float* __restrict__ bias,
             float* __restrict__ out)
{
    extern __shared__ float smem[];
    float* Ws  = smem;                        // [i][p][o] (o contiguous)
    float* xsb[2];
    xsb[0] = smem + WS_FLOATS;
    xsb[1] = xsb[0] + XS_FLOATS;
    float* ysb[2];
    ysb[0] = xsb[1] + XS_FLOATS;              // [p][NVOX]
    ysb[1] = ysb[0] + YS_FLOATS;

    const int tid = threadIdx.x;
    const int b   = blockIdx.y;
    const int t   = blockIdx.x;
    const int tz  = t / 36;
    const int ty  = (t % 36) / 6;
    const int tx  = t % 6;
    const int z0  = tz * TILE, y0 = ty * TILE, x0 = tx * TILE;

    // ---- preload all W into smem: Ws[(i*NP+p)*NO + o] = wg[o][i][p] ----
    for (int idx = tid; idx < WS_FLOATS; idx += NTHR) {
        int o = idx / (NI * NP);
        int r = idx % (NI * NP);
        Ws[r * NO + o] = wg[idx];
    }

    const size_t x_chan = (size_t)DIMS * DIMS * DIMS;   // 110592
    const float* xb = x + (size_t)b * NI * x_chan;

    // GEMM thread tile: 8 outputs x 8 voxels
    const int og = tid & 7;
    const int vg = tid >> 3;        // 0..63
    const int o0 = og * 8;
    const int v0 = vg * 8;

    float2 acc[32];
    #pragma unroll
    for (int k = 0; k < 32; k++) acc[k] = make_float2(0.f, 0.f);

    // halo-tile prefetch (gmem -> regs), 4 elems per thread
    float pre[4];
    auto do_prefetch = [&](int ci) {
        const float* xc = xb + (size_t)ci * x_chan;
        #pragma unroll
        for (int k = 0; k < 4; k++) {
            int idx = tid + k * NTHR;
            float v = 0.0f;
            if (idx < XS_FLOATS) {
                int zz = idx / (HALO * HALO);
                int rr = idx % (HALO * HALO);
                int yy = rr / HALO, xx = rr % HALO;
                int gz = z0 + zz - 2, gy = y0 + yy - 2, gx = x0 + xx - 2;
                if ((unsigned)gz < (unsigned)DIMS &&
                    (unsigned)gy < (unsigned)DIMS &&
                    (unsigned)gx < (unsigned)DIMS)
                    v = __ldg(&xc[(gz * DIMS + gy) * DIMS + gx]);
            }
            pre[k] = v;
        }
    };
    auto commit = [&](float* dst) {
        #pragma unroll
        for (int k = 0; k < 4; k++) {
            int idx = tid + k * NTHR;
            if (idx < XS_FLOATS) dst[idx] = pre[k];
        }
    };
    // radial sums: 1 voxel per thread, 125 taps -> 10 classes
    auto radial = [&](const float* xsrc, float* ydst) {
        const int vz = tid >> 6, vy = (tid >> 3) & 7, vx = tid & 7;
        float yr[NP];
        #pragma unroll
        for (int p = 0; p < NP; p++) yr[p] = 0.0f;
        #pragma unroll
        for (int dz = 0; dz < 5; dz++) {
            #pragma unroll
            for (int dy = 0; dy < 5; dy++) {
                const float* row = &xsrc[((vz + dz) * HALO + (vy + dy)) * HALO + vx];
                #pragma unroll
                for (int dx = 0; dx < 5; dx++) {
                    const int p = p_of_r2((dz - 2) * (dz - 2) +
                                          (dy - 2) * (dy - 2) +
                                          (dx - 2) * (dx - 2));
                    yr[p] += row[dx];
                }
            }
        }
        #pragma unroll
        for (int p = 0; p < NP; p++) ydst[p * NVOX + tid] = yr[p];
    };
    // channel-mix GEMM for one input channel
    auto gemm = [&](int ci, const float* ysrc) {
        const float* wbase = &Ws[(ci * NP) * NO];
        #pragma unroll
        for (int p = 0; p < NP; p++) {
            const float4 w0 = *(const float4*)&wbase[p * NO + o0];
            const float4 w1 = *(const float4*)&wbase[p * NO + o0 + 4];
            const float* yrow = &ysrc[p * NVOX + v0];
            const float4 ya = *(const float4*)&yrow[0];
            const float4 yb = *(const float4*)&yrow[4];
            float  wv[8] = { w0.x, w0.y, w0.z, w0.w, w1.x, w1.y, w1.z, w1.w };
            float2 yv[4] = { {ya.x, ya.y}, {ya.z, ya.w}, {yb.x, yb.y}, {yb.z, yb.w} };
            #pragma unroll
            for (int j = 0; j < 8; j++) {
                float2 wj = make_float2(wv[j], wv[j]);
                #pragma unroll
                for (int l = 0; l < 4; l++)
                    acc[j * 4 + l] = ffma2(wj, yv[l], acc[j * 4 + l]);
            }
        }
    };

    // ---- pipeline prologue ----
    do_prefetch(0);
    commit(xsb[0]);
    __syncthreads();              // xs(0) visible
    radial(xsb[0], ysb[0]);       // Ys(0)
    do_prefetch(1);
    commit(xsb[1]);
    __syncthreads();              // Ys(0) + xs(1) visible

    // ---- steady state: 1 barrier per ci; radial(ci+1) overlaps GEMM(ci) ----
    #pragma unroll 1
    for (int ci = 0; ci < NI; ci++) {
        const int cur = ci & 1;
        if (ci + 2 < NI) do_prefetch(ci + 2);            // LDGs in flight
        if (ci + 1 < NI) radial(xsb[cur ^ 1], ysb[cur ^ 1]);  // LSU-heavy
        gemm(ci, ysb[cur]);                              // FMA-heavy (overlaps)
        if (ci + 2 < NI) commit(xsb[cur]);               // overwrite consumed xs
        __syncthreads();
    }

    // ---- epilogue: out = Y0*acc + bias ----
    const int vz = vg >> 3, vy = vg & 7;
    const float2 scl = make_float2(Y0C, Y0C);
    #pragma unroll
    for (int j = 0; j < 8; j++) {
        const float bb = __ldg(&bias[o0 + j]);
        const float2 bp = make_float2(bb, bb);
        float* dst = out + ((size_t)(b * NO + o0 + j)) * x_chan
                         + ((size_t)(z0 + vz) * DIMS + (y0 + vy)) * DIMS + x0;
        float2 r0 = ffma2(acc[j * 4 + 0], scl, bp);
        float2 r1 = ffma2(acc[j * 4 + 1], scl, bp);
        float2 r2 = ffma2(acc[j * 4 + 2], scl, bp);
        float2 r3 = ffma2(acc[j * 4 + 3], scl, bp);
        float4 s0 = make_float4(r0.x, r0.y, r1.x, r1.y);
        float4 s1 = make_float4(r2.x, r2.y, r3.x, r3.y);
        *(float4*)&dst[0] = s0;
        *(float4*)&dst[4] = s1;
    }
}

extern "C" void kernel_launch(void* const* d_in, const int* in_sizes, int n_in,
                              void* d_out, int out_size)
{
    const float* x    = (const float*)d_in[0];   // [2,32,1,48,48,48]
    const float* w    = (const float*)d_in[1];   // [64,32,1,1,1,10]
    const float* bias = (const float*)d_in[2];   // [64]
    float* out = (float*)d_out;                  // [2,64,1,48,48,48]

    cudaFuncSetAttribute(econv_kernel,
                         cudaFuncAttributeMaxDynamicSharedMemorySize, SMEM_BYTES);
    dim3 grid(216, 2);
    econv_kernel<<<grid, NTHR, SMEM_BYTES>>>(x, w, bias, out);
}

// round 4
// speedup vs baseline: 1.1373x; 1.1373x over previous
#include <cuda_runtime.h>

// EquiLocalPatOrientConvolution: B=2, I=32, O=64, D=H=W=48, K=5 (pad 2).
// filter = Y0 * sum_p W[o,i,p] * radial_mask_p (masks partition 125 taps).
// v4: 256-thr blocks, tile 8x8x4, W transposed to __device__ global (Y0 folded),
// 2.5KB/ci W slice double-buffered in smem -> smem 24.6KB, 2 blocks/SM.

#define DIMS   48
#define TX     8
#define TY     8
#define TZ     4
#define HX     12
#define HY     12
#define HZ     8
#define NI     32
#define NO     64
#define NP     10
#define Y0C    0.28209479177387814f
#define NTHR   256
#define NVOX   256                       // TX*TY*TZ

__device__ __host__ constexpr int p_of_r2(int r2) {
    return r2 <= 6 ? r2 : (r2 == 8 ? 7 : (r2 == 9 ? 8 : 9));
}

#define XS_FLOATS  (HX * HY * HZ)        // 1152
#define YS_FLOATS  (NP * NVOX)           // 2560
#define WCI_FLOATS (NP * NO)             // 640
#define SMEM_FLOATS (2 * XS_FLOATS + YS_FLOATS + 2 * WCI_FLOATS)
#define SMEM_BYTES  (SMEM_FLOATS * 4)    // 24704

__device__ float g_Wt[NI * NP * NO];     // [(ci*NP+p)*NO + o], Y0 pre-folded

__device__ __forceinline__ float2 ffma2(float2 a, float2 b, float2 c) {
    unsigned long long ua = *reinterpret_cast<unsigned long long*>(&a);
    unsigned long long ub = *reinterpret_cast<unsigned long long*>(&b);
    unsigned long long uc = *reinterpret_cast<unsigned long long*>(&c);
    unsigned long long ud;
    asm("fma.rn.f32x2 %0, %1, %2, %3;" : "=l"(ud) : "l"(ua), "l"(ub), "l"(uc));
    return *reinterpret_cast<float2*>(&ud);
}

__global__ void wt_kernel(const float* __restrict__ wg) {
    int idx = blockIdx.x * 256 + threadIdx.x;          // over (i*NP+p)*NO+o
    if (idx < NI * NP * NO) {
        int o = idx & 63;
        int r = idx >> 6;                              // i*NP+p
        g_Wt[idx] = Y0C * wg[o * (NI * NP) + r];
    }
}

__global__ void __launch_bounds__(NTHR, 2)
econv_kernel(const float* __restrict__ x,
             const float* __restrict__ bias,
             float* __restrict__ out)
{
    extern __shared__ float smem[];
    float* xsb[2]; xsb[0] = smem;            xsb[1] = xsb[0] + XS_FLOATS;
    float* Ys = xsb[1] + XS_FLOATS;                    // [p][NVOX]
    float* wsb[2]; wsb[0] = Ys + YS_FLOATS;  wsb[1] = wsb[0] + WCI_FLOATS;

    const int tid = threadIdx.x;
    const int b   = blockIdx.y;
    const int t   = blockIdx.x;
    const int tz  = t / 36;
    const int ty  = (t % 36) / 6;
    const int tx  = t % 6;
    const int z0  = tz * TZ, y0 = ty * TY, x0 = tx * TX;

    const size_t x_chan = (size_t)DIMS * DIMS * DIMS;  // 110592
    const float* xb = x + (size_t)b * NI * x_chan;

    // GEMM thread tile: 8 outputs x 8 voxels (one x-row)
    const int og = tid & 7;
    const int vg = tid >> 3;                 // 0..31
    const int o0 = og * 8;
    const int v0 = vg * 8;

    float2 acc[32];
    #pragma unroll
    for (int k = 0; k < 32; k++) acc[k] = make_float2(0.f, 0.f);

    // ---- prefetch helpers (gmem -> regs -> smem) ----
    float pre[5];                            // halo: 1152/256 = 4.5
    auto pf_x = [&](int ci) {
        const float* xc = xb + (size_t)ci * x_chan;
        #pragma unroll
        for (int k = 0; k < 5; k++) {
            int idx = tid + k * NTHR;
            float v = 0.0f;
            if (idx < XS_FLOATS) {
                int zz = idx / (HX * HY);
                int rr = idx % (HX * HY);
                int yy = rr / HX, xx = rr % HX;
                int gz = z0 + zz - 2, gy = y0 + yy - 2, gx = x0 + xx - 2;
                if ((unsigned)gz < (unsigned)DIMS &&
                    (unsigned)gy < (unsigned)DIMS &&
                    (unsigned)gx < (unsigned)DIMS)
                    v = __ldg(&xc[(gz * DIMS + gy) * DIMS + gx]);
            }
            pre[k] = v;
        }
    };
    auto cm_x = [&](float* dst) {
        #pragma unroll
        for (int k = 0; k < 5; k++) {
            int idx = tid + k * NTHR;
            if (idx < XS_FLOATS) dst[idx] = pre[k];
        }
    };
    float wpre[3];                           // 640/256 = 2.5
    auto pf_w = [&](int ci) {
        const float* src = &g_Wt[ci * WCI_FLOATS];
        #pragma unroll
        for (int k = 0; k < 3; k++) {
            int idx = tid + k * NTHR;
            wpre[k] = (idx < WCI_FLOATS) ? __ldg(&src[idx]) : 0.f;
        }
    };
    auto cm_w = [&](float* dst) {
        #pragma unroll
        for (int k = 0; k < 3; k++) {
            int idx = tid + k * NTHR;
            if (idx < WCI_FLOATS) dst[idx] = wpre[k];
        }
    };

    // ---- radial sums: 1 voxel/thread, 125 taps -> 10 r^2 classes ----
    auto radial = [&](const float* xsrc) {
        const int vz = tid >> 6, vy = (tid >> 3) & 7, vx = tid & 7;
        float yr[NP];
        #pragma unroll
        for (int p = 0; p < NP; p++) yr[p] = 0.0f;
        #pragma unroll
        for (int dz = 0; dz < 5; dz++) {
            #pragma unroll
            for (int dy = 0; dy < 5; dy++) {
                const float* row = &xsrc[((vz + dz) * HY + (vy + dy)) * HX + vx];
                #pragma unroll
                for (int dx = 0; dx < 5; dx++) {
                    const int p = p_of_r2((dz - 2) * (dz - 2) +
                                          (dy - 2) * (dy - 2) +
                                          (dx - 2) * (dx - 2));
                    yr[p] += row[dx];
                }
            }
        }
        #pragma unroll
        for (int p = 0; p < NP; p++) Ys[p * NVOX + tid] = yr[p];
    };

    // ---- GEMM: acc[j][l] += W[ci][p][o0+j] * Y[p][v0+2l..] ----
    auto gemm = [&](const float* wci) {
        #pragma unroll
        for (int p = 0; p < NP; p++) {
            const float4 w0 = *(const float4*)&wci[p * NO + o0];
            const float4 w1 = *(const float4*)&wci[p * NO + o0 + 4];
            const float* yrow = &Ys[p * NVOX + v0];
            const float4 ya = *(const float4*)&yrow[0];
            const float4 yb = *(const float4*)&yrow[4];
            float  wv[8] = { w0.x, w0.y, w0.z, w0.w, w1.x, w1.y, w1.z, w1.w };
            float2 yv[4] = { {ya.x, ya.y}, {ya.z, ya.w}, {yb.x, yb.y}, {yb.z, yb.w} };
            #pragma unroll
            for (int j = 0; j < 8; j++) {
                float2 wj = make_float2(wv[j], wv[j]);
                #pragma unroll
                for (int l = 0; l < 4; l++)
                    acc[j * 4 + l] = ffma2(wj, yv[l], acc[j * 4 + l]);
            }
        }
    };

    // ---- prologue ----
    pf_x(0); cm_x(xsb[0]);
    pf_w(0); cm_w(wsb[0]);
    __syncthreads();                 // xs(0), W(0) visible
    radial(xsb[0]);                  // Ys(0)

    // ---- main loop: 2 barriers per ci ----
    #pragma unroll 1
    for (int ci = 0; ci < NI; ci++) {
        const int cur = ci & 1;
        if (ci + 1 < NI) { pf_x(ci + 1); pf_w(ci + 1); }  // LDGs in flight
        __syncthreads();             // Ys(ci) ready
        gemm(wsb[cur]);
        if (ci + 1 < NI) {
            cm_x(xsb[cur ^ 1]);
            cm_w(wsb[cur ^ 1]);
            __syncthreads();         // new xs/W visible; gemm done with Ys
            radial(xsb[cur ^ 1]);    // build Ys(ci+1)
        }
    }

    // ---- epilogue: out = acc + bias (Y0 folded into W) ----
    const int vz = vg >> 3, vy = vg & 7;
    #pragma unroll
    for (int j = 0; j < 8; j++) {
        const float bb = __ldg(&bias[o0 + j]);
        float* dst = out + ((size_t)(b * NO + o0 + j)) * x_chan
                         + ((size_t)(z0 + vz) * DIMS + (y0 + vy)) * DIMS + x0;
        float4 s0 = make_float4(acc[j*4+0].x + bb, acc[j*4+0].y + bb,
                                acc[j*4+1].x + bb, acc[j*4+1].y + bb);
        float4 s1 = make_float4(acc[j*4+2].x + bb, acc[j*4+2].y + bb,
                                acc[j*4+3].x + bb, acc[j*4+3].y + bb);
        *(float4*)&dst[0] = s0;
        *(float4*)&dst[4] = s1;
    }
}

extern "C" void kernel_launch(void* const* d_in, const int* in_sizes, int n_in,
                              void* d_out, int out_size)
{
    const float* x    = (const float*)d_in[0];   // [2,32,1,48,48,48]
    const float* w    = (const float*)d_in[1];   // [64,32,1,1,1,10]
    const float* bias = (const float*)d_in[2];   // [64]
    float* out = (float*)d_out;                  // [2,64,1,48,48,48]

    wt_kernel<<<(NI * NP * NO + 255) / 256, 256>>>(w);

    dim3 grid(432, 2);                           // 6x6x12 tiles x batch
    econv_kernel<<<grid, NTHR, SMEM_BYTES>>>(x, bias, out);
}